// round 5
// baseline (speedup 1.0000x reference)
#include <cuda_runtime.h>
#include <cuda_bf16.h>

#define ND 5000
#define NR 7000
#define NN 12000           // total nodes
#define DD 64              // embedding dim
#define NW 375             // 12000/32 words per bitmask row

// ---------------- device scratch (static, no allocation) ----------------
__device__ unsigned g_bits[NN * NW];      // 18 MB adjacency bitmask (dedup!)
__device__ int      g_deg[NN];
__device__ float    g_dinv[NN];
__device__ int      g_off[NN + 1];
__device__ int      g_cols[1000000];      // nnz <= 2E = 1,000,000
__device__ float    g_x0[NN * DD];
__device__ float    g_x1[NN * DD];

// ---------------- kernels ----------------

// zero the bitmask (4,500,000 words, divisible by 4 -> uint4 stores)
__global__ void zero_bits_kernel() {
    int i = blockIdx.x * blockDim.x + threadIdx.x;
    if (i < NN * NW / 4) {
        uint4 z = make_uint4(0u, 0u, 0u, 0u);
        reinterpret_cast<uint4*>(g_bits)[i] = z;
    }
}

// set bits (s,d) and (d,s). atomicOr is idempotent -> duplicates collapse,
// exactly matching the reference's scatter-set semantics.
__global__ void edge_kernel(const int* __restrict__ ei, int E) {
    int e = blockIdx.x * blockDim.x + threadIdx.x;
    if (e >= E) return;
    int s = ei[e];
    int d = ei[E + e];
    atomicOr(&g_bits[s * NW + (d >> 5)], 1u << (d & 31));
    atomicOr(&g_bits[d * NW + (s >> 5)], 1u << (s & 31));
}

// warp per row: popcount degree + d^{-1/2}
__global__ void degree_kernel() {
    int warp = (blockIdx.x * blockDim.x + threadIdx.x) >> 5;
    int lane = threadIdx.x & 31;
    if (warp >= NN) return;
    const unsigned* row = g_bits + warp * NW;
    int s = 0;
    for (int w = lane; w < NW; w += 32) s += __popc(row[w]);
    #pragma unroll
    for (int o = 16; o; o >>= 1) s += __shfl_down_sync(0xFFFFFFFFu, s, o);
    if (lane == 0) {
        g_deg[warp] = s;
        g_dinv[warp] = 1.0f / sqrtf((float)s + 1e-12f);
    }
}

// single-block exclusive scan of g_deg -> g_off (12000 elements)
__global__ void scan_kernel() {
    const int T = 1024, PER = 12;                 // 12*1024 = 12288 >= 12000
    __shared__ int warpsum[32];
    int t = threadIdx.x;
    int lane = t & 31, wid = t >> 5;
    int local[PER];
    int s = 0;
    #pragma unroll
    for (int i = 0; i < PER; i++) {
        int idx = t * PER + i;
        int v = (idx < NN) ? g_deg[idx] : 0;
        local[i] = s;                             // thread-local exclusive
        s += v;
    }
    // warp inclusive scan of per-thread totals
    int pre = s;
    #pragma unroll
    for (int o = 1; o < 32; o <<= 1) {
        int n = __shfl_up_sync(0xFFFFFFFFu, pre, o);
        if (lane >= o) pre += n;
    }
    if (lane == 31) warpsum[wid] = pre;
    __syncthreads();
    if (wid == 0) {
        int v = warpsum[lane];
        #pragma unroll
        for (int o = 1; o < 32; o <<= 1) {
            int n = __shfl_up_sync(0xFFFFFFFFu, v, o);
            if (lane >= o) v += n;
        }
        warpsum[lane] = v;
    }
    __syncthreads();
    int base = (wid > 0 ? warpsum[wid - 1] : 0) + (pre - s);  // global exclusive
    #pragma unroll
    for (int i = 0; i < PER; i++) {
        int idx = t * PER + i;
        if (idx < NN) g_off[idx] = base + local[i];
    }
    if (t == T - 1) g_off[NN] = base + s;         // total nnz
    (void)T;
}

// warp per row: extract set bits into CSR col array (order irrelevant for sum)
__global__ void fill_kernel() {
    int warp = (blockIdx.x * blockDim.x + threadIdx.x) >> 5;
    int lane = threadIdx.x & 31;
    if (warp >= NN) return;
    const unsigned* row = g_bits + warp * NW;
    int pos = g_off[warp];
    for (int wb = 0; wb < NW; wb += 32) {
        int w = wb + lane;
        unsigned word = (w < NW) ? row[w] : 0u;
        int c = __popc(word);
        int pre = c;
        #pragma unroll
        for (int o = 1; o < 32; o <<= 1) {
            int n = __shfl_up_sync(0xFFFFFFFFu, pre, o);
            if (lane >= o) pre += n;
        }
        int p = pos + pre - c;                    // exclusive within stripe
        int base = w * 32;
        while (word) {
            int b = __ffs(word) - 1;
            word &= word - 1;
            g_cols[p++] = base + b;
        }
        pos += __shfl_sync(0xFFFFFFFFu, pre, 31); // stripe total
    }
}

// concat inputs -> g_x0, and seed the layer-sum in d_out (embs[0] term)
__global__ void init_kernel(const float* __restrict__ dis,
                            const float* __restrict__ drug,
                            float* __restrict__ out) {
    int i = blockIdx.x * blockDim.x + threadIdx.x;   // float4 index
    if (i >= NN * DD / 4) return;
    float4 v;
    if (i < ND * DD / 4) v = reinterpret_cast<const float4*>(dis)[i];
    else                 v = reinterpret_cast<const float4*>(drug)[i - ND * DD / 4];
    reinterpret_cast<float4*>(g_x0)[i] = v;
    reinterpret_cast<float4*>(out)[i]  = v;
}

// one block (64 threads = one dim each) per row; neighbors staged in shared.
// dir=0: x0 -> x1,  dir=1: x1 -> x0.  Accumulates layer output into `acc`.
__global__ void spmm_kernel(int dir, float* __restrict__ acc) {
    __shared__ int   s_col[64];
    __shared__ float s_w[64];
    const float* __restrict__ xin = dir ? g_x1 : g_x0;
    float* __restrict__ xout      = dir ? g_x0 : g_x1;

    int row = blockIdx.x;
    int d = threadIdx.x;
    int beg = g_off[row], end = g_off[row + 1];
    float a = 0.0f;
    for (int k0 = beg; k0 < end; k0 += 64) {
        int kk = k0 + d;
        if (kk < end) {
            int j = g_cols[kk];
            s_col[d] = j;
            s_w[d] = g_dinv[j];
        }
        __syncthreads();
        int cnt = min(64, end - k0);
        for (int t = 0; t < cnt; t++)
            a += s_w[t] * xin[s_col[t] * DD + d];
        __syncthreads();
    }
    float y = g_dinv[row] * a;
    xout[row * DD + d] = y;
    acc[row * DD + d] += y;
}

// mean over the 4 stacked embeddings
__global__ void scale_kernel(float* __restrict__ out) {
    int i = blockIdx.x * blockDim.x + threadIdx.x;
    if (i < NN * DD) out[i] *= 0.25f;
}

// ---------------- launch ----------------
extern "C" void kernel_launch(void* const* d_in, const int* in_sizes, int n_in,
                              void* d_out, int out_size) {
    const float* dis  = (const float*)d_in[0];
    const float* drug = (const float*)d_in[1];
    const int*   ei   = (const int*)d_in[2];
    int E = in_sizes[2] / 2;
    float* out = (float*)d_out;

    zero_bits_kernel<<<(NN * NW / 4 + 255) / 256, 256>>>();
    edge_kernel<<<(E + 255) / 256, 256>>>(ei, E);
    degree_kernel<<<(NN * 32 + 255) / 256, 256>>>();
    scan_kernel<<<1, 1024>>>();
    fill_kernel<<<(NN * 32 + 255) / 256, 256>>>();
    init_kernel<<<(NN * DD / 4 + 255) / 256, 256>>>(dis, drug, out);

    spmm_kernel<<<NN, 64>>>(0, out);   // layer 1: x0 -> x1
    spmm_kernel<<<NN, 64>>>(1, out);   // layer 2: x1 -> x0
    spmm_kernel<<<NN, 64>>>(0, out);   // layer 3: x0 -> x1

    scale_kernel<<<(NN * DD + 255) / 256, 256>>>(out);
}

// round 11
// speedup vs baseline: 1.2684x; 1.2684x over previous
#include <cuda_runtime.h>
#include <cuda_fp16.h>

#define ND 5000
#define NR 7000
#define NN 12000           // total nodes
#define DD 64              // embedding dim
#define NW 375             // 12000/32 bitmask words per row
#define SELL 256           // ELL stride (max degree ~19 sigma margin)

// ---------------- device scratch (static, no allocation) ----------------
__device__ unsigned g_bits[NN * NW];       // 18 MB adjacency bitmask (dedup)
__device__ int      g_deg[NN];
__device__ float    g_dinv[NN];
__device__ int      g_cols[NN * SELL];     // ELL columns, 12.3 MB
__device__ __half2  g_xa[NN * 32];         // ping (64 half dims = 32 half2)
__device__ __half2  g_xb[NN * 32];         // pong

// ---------------- kernels ----------------

// zero the bitmask (4.5M words, /4 -> uint4 stores)
__global__ void zero_bits_kernel() {
    int i = blockIdx.x * blockDim.x + threadIdx.x;
    if (i < NN * NW / 4)
        reinterpret_cast<uint4*>(g_bits)[i] = make_uint4(0u, 0u, 0u, 0u);
}

// set bits (s,d) and (d,s). atomicOr idempotent -> duplicates collapse,
// matching the reference scatter-set semantics exactly.
__global__ void edge_kernel(const int* __restrict__ ei, int E) {
    int e = blockIdx.x * blockDim.x + threadIdx.x;
    if (e >= E) return;
    int s = ei[e];
    int d = ei[E + e];
    atomicOr(&g_bits[s * NW + (d >> 5)], 1u << (d & 31));
    atomicOr(&g_bits[d * NW + (s >> 5)], 1u << (s & 31));
}

// ONE pass over the bitmask: warp per row extracts set bits into ELL slots,
// computes degree and d^{-1/2}. (replaces degree_kernel + scan_kernel + fill)
__global__ void fill_kernel() {
    int warp = (blockIdx.x * blockDim.x + threadIdx.x) >> 5;
    int lane = threadIdx.x & 31;
    if (warp >= NN) return;
    const unsigned* row = g_bits + warp * NW;
    int* cols = g_cols + warp * SELL;
    int pos = 0;
    for (int wb = 0; wb < NW; wb += 32) {
        int w = wb + lane;
        unsigned word = (w < NW) ? row[w] : 0u;
        int c = __popc(word);
        int pre = c;
        #pragma unroll
        for (int o = 1; o < 32; o <<= 1) {
            int n = __shfl_up_sync(0xFFFFFFFFu, pre, o);
            if (lane >= o) pre += n;
        }
        int p = pos + pre - c;                 // exclusive within stripe
        int base = w * 32;
        while (word) {
            int b = __ffs(word) - 1;
            word &= word - 1;
            if (p < SELL) cols[p] = base + b;
            p++;
        }
        pos += __shfl_sync(0xFFFFFFFFu, pre, 31);
    }
    if (lane == 0) {
        g_deg[warp] = pos;
        g_dinv[warp] = 1.0f / sqrtf((float)pos + 1e-12f);
    }
}

// concat inputs -> half ping buffer, seed layer-sum (embs[0], exact fp32) in out
__global__ void init_kernel(const float* __restrict__ dis,
                            const float* __restrict__ drug,
                            float* __restrict__ out) {
    int i = blockIdx.x * blockDim.x + threadIdx.x;  // float2 index
    if (i >= NN * 32) return;
    float2 v = (i < ND * 32) ? reinterpret_cast<const float2*>(dis)[i]
                             : reinterpret_cast<const float2*>(drug)[i - ND * 32];
    g_xa[i] = __floats2half2_rn(v.x, v.y);
    reinterpret_cast<float2*>(out)[i] = v;
}

// warp per row, lane = 2 dims (half2). Neighbor cols/weights staged in regs,
// broadcast by shuffle. Fixed 32-wide inner loop fully unrolled (inactive
// lanes: w=0, j=0 -> row-0 gather, L1-resident). Accumulates fp32 into acc;
// sc = 1 for middle layers, 0.25 on the final layer (fused mean).
__global__ void spmm_kernel(int dir, float* __restrict__ acc, float sc) {
    const __half2* __restrict__ xin = dir ? g_xb : g_xa;
    __half2* __restrict__ xout      = dir ? g_xa : g_xb;

    int warp = (blockIdx.x * blockDim.x + threadIdx.x) >> 5;
    int lane = threadIdx.x & 31;
    if (warp >= NN) return;
    int deg = g_deg[warp];
    const int* cols = g_cols + warp * SELL;

    float ax = 0.0f, ay = 0.0f;
    for (int k0 = 0; k0 < deg; k0 += 32) {
        int kk = k0 + lane;
        int j = 0;
        float w = 0.0f;
        if (kk < deg) {
            j = cols[kk];
            w = g_dinv[j];
        }
        #pragma unroll
        for (int t = 0; t < 32; t++) {
            int   jj = __shfl_sync(0xFFFFFFFFu, j, t);
            float ww = __shfl_sync(0xFFFFFFFFu, w, t);
            float2 v = __half22float2(xin[jj * 32 + lane]);
            ax = fmaf(ww, v.x, ax);
            ay = fmaf(ww, v.y, ay);
        }
    }
    float di = g_dinv[warp];
    ax *= di;
    ay *= di;
    int idx = warp * 32 + lane;
    xout[idx] = __floats2half2_rn(ax, ay);
    float2* ap = reinterpret_cast<float2*>(acc) + idx;
    float2 pr = *ap;
    pr.x = (pr.x + ax) * sc;
    pr.y = (pr.y + ay) * sc;
    *ap = pr;
}

// ---------------- launch ----------------
extern "C" void kernel_launch(void* const* d_in, const int* in_sizes, int n_in,
                              void* d_out, int out_size) {
    const float* dis  = (const float*)d_in[0];
    const float* drug = (const float*)d_in[1];
    const int*   ei   = (const int*)d_in[2];
    int E = in_sizes[2] / 2;
    float* out = (float*)d_out;

    zero_bits_kernel<<<(NN * NW / 4 + 255) / 256, 256>>>();
    edge_kernel<<<(E + 255) / 256, 256>>>(ei, E);
    fill_kernel<<<(NN * 32 + 255) / 256, 256>>>();
    init_kernel<<<(NN * 32 + 255) / 256, 256>>>(dis, drug, out);

    const int SPMM_GRID = (NN * 32 + 255) / 256;     // warp per row, 256 thr/blk
    spmm_kernel<<<SPMM_GRID, 256>>>(0, out, 1.0f);   // layer 1: xa -> xb
    spmm_kernel<<<SPMM_GRID, 256>>>(1, out, 1.0f);   // layer 2: xb -> xa
    spmm_kernel<<<SPMM_GRID, 256>>>(0, out, 0.25f);  // layer 3 + fused mean
}

// round 15
// speedup vs baseline: 1.3640x; 1.0754x over previous
#include <cuda_runtime.h>
#include <cuda_fp16.h>

#define ND 5000
#define NR 7000
#define NN 12000           // total nodes
#define NNP (NN + 1)       // + zero pad row for inactive-lane gathers
#define DD 64              // embedding dim
#define NW 375             // 12000/32 bitmask words per row
#define SELL 256           // ELL stride (max degree ~19 sigma margin)

// ---------------- device scratch (static, no allocation) ----------------
__device__ unsigned g_bits[NN * NW];       // 18 MB adjacency bitmask (dedup)
__device__ int      g_deg[NN];
__device__ float    g_dinv[NN];
__device__ int      g_cols[NN * SELL];     // ELL columns, 12.3 MB
__device__ __half2  g_ua[NNP * 32];        // ping: u = D^-1/2 x (64 halfs/row)
__device__ __half2  g_ub[NNP * 32];        // pong

// ---------------- kernels ----------------

// zero the bitmask (4.5M words, /4 -> uint4) + the pad rows of u buffers
__global__ void zero_kernel() {
    int i = blockIdx.x * blockDim.x + threadIdx.x;
    if (i < NN * NW / 4)
        reinterpret_cast<uint4*>(g_bits)[i] = make_uint4(0u, 0u, 0u, 0u);
    if (i < 32) {
        g_ua[NN * 32 + i] = __floats2half2_rn(0.0f, 0.0f);
        g_ub[NN * 32 + i] = __floats2half2_rn(0.0f, 0.0f);
    }
}

// set bits (s,d) and (d,s). atomicOr idempotent -> duplicates collapse,
// matching the reference scatter-set semantics exactly.
__global__ void edge_kernel(const int* __restrict__ ei, int E) {
    int e = blockIdx.x * blockDim.x + threadIdx.x;
    if (e >= E) return;
    int s = ei[e];
    int d = ei[E + e];
    atomicOr(&g_bits[s * NW + (d >> 5)], 1u << (d & 31));
    atomicOr(&g_bits[d * NW + (s >> 5)], 1u << (s & 31));
}

// ONE pass over the bitmask: warp per row extracts set bits into ELL slots,
// computes degree + d^{-1/2}, then (fused) seeds u0 = dinv*x (half) and the
// fp32 layer-sum accumulator out = x0.
__global__ void fill_kernel(const float* __restrict__ dis,
                            const float* __restrict__ drug,
                            float* __restrict__ out) {
    int warp = (blockIdx.x * blockDim.x + threadIdx.x) >> 5;
    int lane = threadIdx.x & 31;
    if (warp >= NN) return;
    const unsigned* row = g_bits + warp * NW;
    int* cols = g_cols + warp * SELL;
    int pos = 0;
    for (int wb = 0; wb < NW; wb += 32) {
        int w = wb + lane;
        unsigned word = (w < NW) ? row[w] : 0u;
        int c = __popc(word);
        int pre = c;
        #pragma unroll
        for (int o = 1; o < 32; o <<= 1) {
            int n = __shfl_up_sync(0xFFFFFFFFu, pre, o);
            if (lane >= o) pre += n;
        }
        int p = pos + pre - c;                 // exclusive within stripe
        int base = w * 32;
        while (word) {
            int b = __ffs(word) - 1;
            word &= word - 1;
            if (p < SELL) cols[p] = base + b;
            p++;
        }
        pos += __shfl_sync(0xFFFFFFFFu, pre, 31);
    }
    float dinv = 1.0f / sqrtf((float)pos + 1e-12f);
    if (lane == 0) {
        g_deg[warp] = pos;
        g_dinv[warp] = dinv;
    }
    // fused init: lane covers float2 slot (warp*32 + lane) of the x matrix
    int idx = warp * 32 + lane;
    float2 v = (warp < ND) ? reinterpret_cast<const float2*>(dis)[idx]
                           : reinterpret_cast<const float2*>(drug)[idx - ND * 32];
    reinterpret_cast<float2*>(out)[idx] = v;          // embs[0] term, exact fp32
    float us = (pos > 0) ? dinv : 0.0f;               // avoid inf in fp16
    g_ua[idx] = __floats2half2_rn(v.x * us, v.y * us);
}

// Propagation in u-space: y_i = dinv_i * sum_{j in N(i)} u_j  (UNWEIGHTED sum;
// no per-neighbor dinv gather, no weight shuffle). u_{k+1} = dinv_i * y_i.
// Grid-stride warp-per-row; inactive lanes gather the zeroed pad row NN.
// acc += y; sc = 0.25 on the final layer (fused mean), last skips u store.
__global__ void spmm_kernel(int dir, float* __restrict__ acc, float sc, int last) {
    const __half2* __restrict__ uin = dir ? g_ub : g_ua;
    __half2* __restrict__ uout      = dir ? g_ua : g_ub;

    int warp0 = (blockIdx.x * blockDim.x + threadIdx.x) >> 5;
    int nwarp = (gridDim.x * blockDim.x) >> 5;
    int lane = threadIdx.x & 31;

    for (int row = warp0; row < NN; row += nwarp) {
        int deg = g_deg[row];
        const int* cols = g_cols + row * SELL;
        float ax = 0.0f, ay = 0.0f;
        for (int k0 = 0; k0 < deg; k0 += 32) {
            int kk = k0 + lane;
            int j = (kk < deg) ? cols[kk] : NN;      // pad row -> zeros
            #pragma unroll
            for (int t = 0; t < 32; t++) {
                int jj = __shfl_sync(0xFFFFFFFFu, j, t);
                float2 v = __half22float2(uin[jj * 32 + lane]);
                ax += v.x;
                ay += v.y;
            }
        }
        float di = g_dinv[row];
        float yx = di * ax, yy = di * ay;            // x_{k+1} row
        int idx = row * 32 + lane;
        float2* ap = reinterpret_cast<float2*>(acc) + idx;
        float2 pr = *ap;
        pr.x = (pr.x + yx) * sc;
        pr.y = (pr.y + yy) * sc;
        *ap = pr;
        if (!last)
            uout[idx] = __floats2half2_rn(di * yx, di * yy);  // u_{k+1}
    }
}

// ---------------- launch ----------------
extern "C" void kernel_launch(void* const* d_in, const int* in_sizes, int n_in,
                              void* d_out, int out_size) {
    const float* dis  = (const float*)d_in[0];
    const float* drug = (const float*)d_in[1];
    const int*   ei   = (const int*)d_in[2];
    int E = in_sizes[2] / 2;
    float* out = (float*)d_out;

    zero_kernel<<<(NN * NW / 4 + 255) / 256, 256>>>();
    edge_kernel<<<(E + 255) / 256, 256>>>(ei, E);
    fill_kernel<<<(NN * 32 + 255) / 256, 256>>>(dis, drug, out);

    const int SPMM_GRID = 592;                       // 148 SMs x 4 blocks, 1 wave
    spmm_kernel<<<SPMM_GRID, 256>>>(0, out, 1.0f, 0);   // layer 1: ua -> ub
    spmm_kernel<<<SPMM_GRID, 256>>>(1, out, 1.0f, 0);   // layer 2: ub -> ua
    spmm_kernel<<<SPMM_GRID, 256>>>(0, out, 0.25f, 1);  // layer 3 + fused mean
}

// round 16
// speedup vs baseline: 1.6212x; 1.1885x over previous
#include <cuda_runtime.h>
#include <cuda_fp16.h>

#define ND 5000
#define NR 7000
#define NN 12000           // total nodes
#define NNP (NN + 1)       // + zero pad row for inactive-lane gathers
#define DD 64              // embedding dim
#define NW 375             // 12000/32 bitmask words per row
#define SELL 256           // ELL stride (max degree ~19 sigma margin)
#define SPMM_BLOCKS 592    // 148 SMs x 4 blocks
#define SPMM_WARPS (SPMM_BLOCKS * 8)

// ---------------- device scratch (static, no allocation) ----------------
__device__ unsigned g_bits[NN * NW];       // 18 MB adjacency bitmask (dedup)
__device__ int      g_deg[NN];
__device__ float    g_dinv[NN];
__device__ int      g_cols[NN * SELL];     // ELL columns, 12.3 MB
__device__ __half2  g_ua[NNP * 32];        // ping: u = D^-1/2 x (64 halfs/row)
__device__ __half2  g_ub[NNP * 32];        // pong

// ---------------- kernels ----------------

// zero the bitmask (4.5M words, /4 -> uint4) + the pad rows of u buffers
__global__ void zero_kernel() {
    int i = blockIdx.x * blockDim.x + threadIdx.x;
    if (i < NN * NW / 4)
        reinterpret_cast<uint4*>(g_bits)[i] = make_uint4(0u, 0u, 0u, 0u);
    if (i < 32) {
        g_ua[NN * 32 + i] = __floats2half2_rn(0.0f, 0.0f);
        g_ub[NN * 32 + i] = __floats2half2_rn(0.0f, 0.0f);
    }
}

// set bits (s,d) and (d,s). atomicOr idempotent -> duplicates collapse,
// matching the reference scatter-set semantics exactly.
__global__ void edge_kernel(const int* __restrict__ ei, int E) {
    int e = blockIdx.x * blockDim.x + threadIdx.x;
    if (e >= E) return;
    int s = ei[e];
    int d = ei[E + e];
    atomicOr(&g_bits[s * NW + (d >> 5)], 1u << (d & 31));
    atomicOr(&g_bits[d * NW + (s >> 5)], 1u << (s & 31));
}

// ONE pass over the bitmask: warp per row extracts set bits into ELL slots,
// computes degree + d^{-1/2}, then (fused) seeds u0 = dinv*x (half) and the
// fp32 layer-sum accumulator out = x0.
__global__ void fill_kernel(const float* __restrict__ dis,
                            const float* __restrict__ drug,
                            float* __restrict__ out) {
    int warp = (blockIdx.x * blockDim.x + threadIdx.x) >> 5;
    int lane = threadIdx.x & 31;
    if (warp >= NN) return;
    const unsigned* row = g_bits + warp * NW;
    int* cols = g_cols + warp * SELL;
    int pos = 0;
    for (int wb = 0; wb < NW; wb += 32) {
        int w = wb + lane;
        unsigned word = (w < NW) ? row[w] : 0u;
        int c = __popc(word);
        int pre = c;
        #pragma unroll
        for (int o = 1; o < 32; o <<= 1) {
            int n = __shfl_up_sync(0xFFFFFFFFu, pre, o);
            if (lane >= o) pre += n;
        }
        int p = pos + pre - c;                 // exclusive within stripe
        int base = w * 32;
        while (word) {
            int b = __ffs(word) - 1;
            word &= word - 1;
            if (p < SELL) cols[p] = base + b;
            p++;
        }
        pos += __shfl_sync(0xFFFFFFFFu, pre, 31);
    }
    float dinv = 1.0f / sqrtf((float)pos + 1e-12f);
    if (lane == 0) {
        g_deg[warp] = pos;
        g_dinv[warp] = dinv;
    }
    // fused init: lane covers float2 slot (warp*32 + lane) of the x matrix
    int idx = warp * 32 + lane;
    float2 v = (warp < ND) ? reinterpret_cast<const float2*>(dis)[idx]
                           : reinterpret_cast<const float2*>(drug)[idx - ND * 32];
    reinterpret_cast<float2*>(out)[idx] = v;          // embs[0] term, exact fp32
    float us = (pos > 0) ? dinv : 0.0f;               // avoid inf in fp16
    g_ua[idx] = __floats2half2_rn(v.x * us, v.y * us);
}

__device__ __forceinline__ float2 h2tof2(unsigned u) {
    __half2 h;
    *reinterpret_cast<unsigned*>(&h) = u;
    return __half22float2(h);
}

// Propagation in u-space: y_i = dinv_i * sum_{j in N(i)} u_j (unweighted sum).
// Warp split into 4 slots of 8 lanes; each inner step gathers 4 neighbor rows
// with LDG.128 (uint4 = 8 halves per lane) + ONE shuffle -> ~4 instr/nnz.
// fp32 accumulation (8 chains/lane). Cross-slot shfl_xor reduce at row end.
// acc += y (sc=0.25 fused mean on last layer); u_{k+1} = dinv*y stored half.
__global__ void __launch_bounds__(256) spmm_kernel(int dir, float* __restrict__ acc,
                                                   float sc, int last) {
    const __half2* __restrict__ uin = dir ? g_ub : g_ua;
    __half2* __restrict__ uout      = dir ? g_ua : g_ub;

    int warp0 = (blockIdx.x * blockDim.x + threadIdx.x) >> 5;
    int lane = threadIdx.x & 31;
    int slot = lane >> 3;          // 0..3 : which neighbor row this lane serves
    int sub  = lane & 7;           // 0..7 : 16B chunk within the 128B row

    for (int row = warp0; row < NN; row += SPMM_WARPS) {
        int deg = g_deg[row];
        const int* cols = g_cols + row * SELL;
        float2 a0 = {0.f, 0.f}, a1 = {0.f, 0.f}, a2 = {0.f, 0.f}, a3 = {0.f, 0.f};

        for (int k0 = 0; k0 < deg; k0 += 32) {
            int kk = k0 + lane;
            int j = (kk < deg) ? cols[kk] : NN;        // pad row -> zeros
            #pragma unroll
            for (int t = 0; t < 8; t++) {
                int jj = __shfl_sync(0xFFFFFFFFu, j, t * 4 + slot);
                uint4 v = *(reinterpret_cast<const uint4*>(uin + jj * 32) + sub);
                float2 f0 = h2tof2(v.x), f1 = h2tof2(v.y);
                float2 f2 = h2tof2(v.z), f3 = h2tof2(v.w);
                a0.x += f0.x; a0.y += f0.y;
                a1.x += f1.x; a1.y += f1.y;
                a2.x += f2.x; a2.y += f2.y;
                a3.x += f3.x; a3.y += f3.y;
            }
        }
        // reduce the 4 slots (lanes differing in bits 3,4)
        #pragma unroll
        for (int off = 8; off <= 16; off <<= 1) {
            a0.x += __shfl_xor_sync(0xFFFFFFFFu, a0.x, off);
            a0.y += __shfl_xor_sync(0xFFFFFFFFu, a0.y, off);
            a1.x += __shfl_xor_sync(0xFFFFFFFFu, a1.x, off);
            a1.y += __shfl_xor_sync(0xFFFFFFFFu, a1.y, off);
            a2.x += __shfl_xor_sync(0xFFFFFFFFu, a2.x, off);
            a2.y += __shfl_xor_sync(0xFFFFFFFFu, a2.y, off);
            a3.x += __shfl_xor_sync(0xFFFFFFFFu, a3.x, off);
            a3.y += __shfl_xor_sync(0xFFFFFFFFu, a3.y, off);
        }
        float di = g_dinv[row];
        if (lane < 8) {
            // this lane owns dims [sub*8, sub*8+8) of the output row
            float y0 = di * a0.x, y1 = di * a0.y, y2 = di * a1.x, y3 = di * a1.y;
            float y4 = di * a2.x, y5 = di * a2.y, y6 = di * a3.x, y7 = di * a3.y;
            float4* ap = reinterpret_cast<float4*>(acc + row * 64) + sub * 2;
            float4 p0 = ap[0], p1 = ap[1];
            p0.x = (p0.x + y0) * sc; p0.y = (p0.y + y1) * sc;
            p0.z = (p0.z + y2) * sc; p0.w = (p0.w + y3) * sc;
            p1.x = (p1.x + y4) * sc; p1.y = (p1.y + y5) * sc;
            p1.z = (p1.z + y6) * sc; p1.w = (p1.w + y7) * sc;
            ap[0] = p0; ap[1] = p1;
            if (!last) {
                uint4 uv;
                __half2 h;
                h = __floats2half2_rn(di * y0, di * y1); uv.x = *reinterpret_cast<unsigned*>(&h);
                h = __floats2half2_rn(di * y2, di * y3); uv.y = *reinterpret_cast<unsigned*>(&h);
                h = __floats2half2_rn(di * y4, di * y5); uv.z = *reinterpret_cast<unsigned*>(&h);
                h = __floats2half2_rn(di * y6, di * y7); uv.w = *reinterpret_cast<unsigned*>(&h);
                *(reinterpret_cast<uint4*>(uout + row * 32) + sub) = uv;
            }
        }
    }
}

// ---------------- launch ----------------
extern "C" void kernel_launch(void* const* d_in, const int* in_sizes, int n_in,
                              void* d_out, int out_size) {
    const float* dis  = (const float*)d_in[0];
    const float* drug = (const float*)d_in[1];
    const int*   ei   = (const int*)d_in[2];
    int E = in_sizes[2] / 2;
    float* out = (float*)d_out;

    zero_kernel<<<(NN * NW / 4 + 255) / 256, 256>>>();
    edge_kernel<<<(E + 255) / 256, 256>>>(ei, E);
    fill_kernel<<<(NN * 32 + 255) / 256, 256>>>(dis, drug, out);

    spmm_kernel<<<SPMM_BLOCKS, 256>>>(0, out, 1.0f, 0);   // layer 1: ua -> ub
    spmm_kernel<<<SPMM_BLOCKS, 256>>>(1, out, 1.0f, 0);   // layer 2: ub -> ua
    spmm_kernel<<<SPMM_BLOCKS, 256>>>(0, out, 0.25f, 1);  // layer 3 + fused mean
}

// round 17
// speedup vs baseline: 1.7256x; 1.0644x over previous
#include <cuda_runtime.h>
#include <cuda_fp16.h>

#define ND 5000
#define NR 7000
#define NN 12000           // total nodes
#define NNP (NN + 1)       // + zero pad row for inactive-lane gathers
#define DD 64              // embedding dim
#define NW 375             // 12000/32 bitmask words per row
#define SELL 256           // ELL stride (max degree ~19 sigma margin)
#define SPMM_BLOCKS 592    // 148 SMs x 4 blocks
#define SPMM_WARPS (SPMM_BLOCKS * 8)

// ---------------- device scratch (static, no allocation) ----------------
__device__ unsigned g_bits[NN * NW];       // 18 MB adjacency bitmask (dedup)
__device__ int      g_deg[NN];
__device__ float    g_dinv[NN];
__device__ int      g_cols[NN * SELL];     // ELL columns, 12.3 MB
__device__ __half2  g_ua[NNP * 32];        // ping: u = D^-1/2 x (64 halfs/row)
__device__ __half2  g_ub[NNP * 32];        // pong

// ---------------- kernels ----------------

// zero the bitmask (4.5M words, /4 -> uint4) + the pad rows of u buffers
__global__ void zero_kernel() {
    int i = blockIdx.x * blockDim.x + threadIdx.x;
    if (i < NN * NW / 4)
        reinterpret_cast<uint4*>(g_bits)[i] = make_uint4(0u, 0u, 0u, 0u);
    if (i < 32) {
        g_ua[NN * 32 + i] = __floats2half2_rn(0.0f, 0.0f);
        g_ub[NN * 32 + i] = __floats2half2_rn(0.0f, 0.0f);
    }
}

// set bits (s,d) and (d,s). atomicOr idempotent -> duplicates collapse,
// matching the reference scatter-set semantics exactly.
__global__ void edge_kernel(const int* __restrict__ ei, int E) {
    int e = blockIdx.x * blockDim.x + threadIdx.x;
    if (e >= E) return;
    int s = ei[e];
    int d = ei[E + e];
    atomicOr(&g_bits[s * NW + (d >> 5)], 1u << (d & 31));
    atomicOr(&g_bits[d * NW + (s >> 5)], 1u << (s & 31));
}

// ONE pass over the bitmask: warp per row extracts set bits into ELL slots,
// computes degree + d^{-1/2}, then (fused) seeds u0 = dinv*x (half) and the
// fp32 layer-sum accumulator out = x0.
__global__ void fill_kernel(const float* __restrict__ dis,
                            const float* __restrict__ drug,
                            float* __restrict__ out) {
    int warp = (blockIdx.x * blockDim.x + threadIdx.x) >> 5;
    int lane = threadIdx.x & 31;
    if (warp >= NN) return;
    const unsigned* row = g_bits + warp * NW;
    int* cols = g_cols + warp * SELL;
    int pos = 0;
    for (int wb = 0; wb < NW; wb += 32) {
        int w = wb + lane;
        unsigned word = (w < NW) ? row[w] : 0u;
        int c = __popc(word);
        int pre = c;
        #pragma unroll
        for (int o = 1; o < 32; o <<= 1) {
            int n = __shfl_up_sync(0xFFFFFFFFu, pre, o);
            if (lane >= o) pre += n;
        }
        int p = pos + pre - c;                 // exclusive within stripe
        int base = w * 32;
        while (word) {
            int b = __ffs(word) - 1;
            word &= word - 1;
            if (p < SELL) cols[p] = base + b;
            p++;
        }
        pos += __shfl_sync(0xFFFFFFFFu, pre, 31);
    }
    float dinv = 1.0f / sqrtf((float)pos + 1e-12f);
    if (lane == 0) {
        g_deg[warp] = pos;
        g_dinv[warp] = dinv;
    }
    // fused init: lane covers float2 slot (warp*32 + lane) of the x matrix
    int idx = warp * 32 + lane;
    float2 v = (warp < ND) ? reinterpret_cast<const float2*>(dis)[idx]
                           : reinterpret_cast<const float2*>(drug)[idx - ND * 32];
    reinterpret_cast<float2*>(out)[idx] = v;          // embs[0] term, exact fp32
    float us = (pos > 0) ? dinv : 0.0f;               // avoid inf in fp16
    g_ua[idx] = __floats2half2_rn(v.x * us, v.y * us);
}

__device__ __forceinline__ __half2 u2h2(unsigned u) {
    return *reinterpret_cast<__half2*>(&u);
}

// Propagation in u-space: y_i = dinv_i * sum_{j in N(i)} u_j (unweighted sum).
// Warp split into 4 slots of 8 lanes; each inner step gathers 4 neighbor rows
// with one LDG.128 + one SHFL. Per-chunk (8 neighbors/lane-slot) accumulation
// in half2 (HADD2), promoted to fp32 once per 32-nnz chunk -> ~2.3 instr/nnz.
// Next chunk's column indices are prefetched before the gather loop.
__global__ void __launch_bounds__(256) spmm_kernel(int dir, float* __restrict__ acc,
                                                   float sc, int last) {
    const __half2* __restrict__ uin = dir ? g_ub : g_ua;
    __half2* __restrict__ uout      = dir ? g_ua : g_ub;

    int warp0 = (blockIdx.x * blockDim.x + threadIdx.x) >> 5;
    int lane = threadIdx.x & 31;
    int slot = lane >> 3;          // 0..3 : which neighbor row this lane serves
    int sub  = lane & 7;           // 0..7 : 16B chunk within the 128B row
    const uint4* ubase = reinterpret_cast<const uint4*>(uin) + sub;  // +jj*8

    for (int row = warp0; row < NN; row += SPMM_WARPS) {
        int deg = g_deg[row];
        float di = g_dinv[row];
        const int* cols = g_cols + row * SELL;
        int nchunk = (deg + 31) >> 5;
        float2 a0 = {0.f, 0.f}, a1 = {0.f, 0.f}, a2 = {0.f, 0.f}, a3 = {0.f, 0.f};

        int j = (lane < deg) ? cols[lane] : NN;          // chunk 0 cols
        for (int c = 0; c < nchunk; c++) {
            int kk = (c + 1) * 32 + lane;                // prefetch chunk c+1
            int jn = (kk < deg) ? cols[kk] : NN;
            __half2 h0 = u2h2(0u), h1 = u2h2(0u), h2 = u2h2(0u), h3 = u2h2(0u);
            #pragma unroll
            for (int t = 0; t < 8; t++) {
                int jj = __shfl_sync(0xFFFFFFFFu, j, t * 4 + slot);
                uint4 v = ubase[jj * 8];
                h0 = __hadd2(h0, u2h2(v.x));
                h1 = __hadd2(h1, u2h2(v.y));
                h2 = __hadd2(h2, u2h2(v.z));
                h3 = __hadd2(h3, u2h2(v.w));
            }
            float2 f;
            f = __half22float2(h0); a0.x += f.x; a0.y += f.y;
            f = __half22float2(h1); a1.x += f.x; a1.y += f.y;
            f = __half22float2(h2); a2.x += f.x; a2.y += f.y;
            f = __half22float2(h3); a3.x += f.x; a3.y += f.y;
            j = jn;
        }
        // reduce the 4 slots (lanes differing in bits 3,4)
        #pragma unroll
        for (int off = 8; off <= 16; off <<= 1) {
            a0.x += __shfl_xor_sync(0xFFFFFFFFu, a0.x, off);
            a0.y += __shfl_xor_sync(0xFFFFFFFFu, a0.y, off);
            a1.x += __shfl_xor_sync(0xFFFFFFFFu, a1.x, off);
            a1.y += __shfl_xor_sync(0xFFFFFFFFu, a1.y, off);
            a2.x += __shfl_xor_sync(0xFFFFFFFFu, a2.x, off);
            a2.y += __shfl_xor_sync(0xFFFFFFFFu, a2.y, off);
            a3.x += __shfl_xor_sync(0xFFFFFFFFu, a3.x, off);
            a3.y += __shfl_xor_sync(0xFFFFFFFFu, a3.y, off);
        }
        if (lane < 8) {
            // this lane owns dims [sub*8, sub*8+8) of the output row
            float y0 = di * a0.x, y1 = di * a0.y, y2 = di * a1.x, y3 = di * a1.y;
            float y4 = di * a2.x, y5 = di * a2.y, y6 = di * a3.x, y7 = di * a3.y;
            float4* ap = reinterpret_cast<float4*>(acc + row * 64) + sub * 2;
            float4 p0 = ap[0], p1 = ap[1];
            p0.x = (p0.x + y0) * sc; p0.y = (p0.y + y1) * sc;
            p0.z = (p0.z + y2) * sc; p0.w = (p0.w + y3) * sc;
            p1.x = (p1.x + y4) * sc; p1.y = (p1.y + y5) * sc;
            p1.z = (p1.z + y6) * sc; p1.w = (p1.w + y7) * sc;
            ap[0] = p0; ap[1] = p1;
            if (!last) {
                uint4 uv;
                __half2 h;
                h = __floats2half2_rn(di * y0, di * y1); uv.x = *reinterpret_cast<unsigned*>(&h);
                h = __floats2half2_rn(di * y2, di * y3); uv.y = *reinterpret_cast<unsigned*>(&h);
                h = __floats2half2_rn(di * y4, di * y5); uv.z = *reinterpret_cast<unsigned*>(&h);
                h = __floats2half2_rn(di * y6, di * y7); uv.w = *reinterpret_cast<unsigned*>(&h);
                *(reinterpret_cast<uint4*>(uout + row * 32) + sub) = uv;
            }
        }
    }
}

// ---------------- launch ----------------
extern "C" void kernel_launch(void* const* d_in, const int* in_sizes, int n_in,
                              void* d_out, int out_size) {
    const float* dis  = (const float*)d_in[0];
    const float* drug = (const float*)d_in[1];
    const int*   ei   = (const int*)d_in[2];
    int E = in_sizes[2] / 2;
    float* out = (float*)d_out;

    zero_kernel<<<(NN * NW / 4 + 255) / 256, 256>>>();
    edge_kernel<<<(E + 255) / 256, 256>>>(ei, E);
    fill_kernel<<<(NN * 32 + 255) / 256, 256>>>(dis, drug, out);

    spmm_kernel<<<SPMM_BLOCKS, 256>>>(0, out, 1.0f, 0);   // layer 1: ua -> ub
    spmm_kernel<<<SPMM_BLOCKS, 256>>>(1, out, 1.0f, 0);   // layer 2: ub -> ua
    spmm_kernel<<<SPMM_BLOCKS, 256>>>(0, out, 0.25f, 1);  // layer 3 + fused mean
}